// round 14
// baseline (speedup 1.0000x reference)
#include <cuda_runtime.h>
#include <cuda_fp16.h>
#include <stdint.h>

#define BATCH 4
#define TT    1024
#define DD    1024
#define HH    8
#define DKK   128
#define PP    2047
#define MHS   (BATCH*TT)
#define BK    32
#define ROWP  40                        // padded smem row stride (halves), BK tiles
#define BUFA  (128*ROWP)
#define BUFB  (64*ROWP)
#define STAGES 3
#define STG   (BUFA + BUFB)
#define DYN   (STAGES*STG*2)            // 46080 B
#define PE_N  (PP*DD)

// stream-B kernels (full K=128 resident)
#define ROWPA 136                       // stride (halves) for K=128 tiles; banks ok
#define SA_HAL (128*ROWPA)              // A stripe: 128 rows
#define SB_HAL (64*ROWPA)               // B tile: 64 rows
#define DYNS  ((SA_HAL + 2*SB_HAL)*2)   // 69632 B

// ---------------- scratch (device globals; all one-term fp16) ----------------
__device__ __half g_hsh[MHS*DD];
__device__ __half g_peh[PE_N];
__device__ __half g_Wqh[DD*DD], g_Wkh[DD*DD], g_Wvh[DD*DD];
__device__ __half g_Woh[DD*DD], g_Wph[DD*DD];
__device__ __half g_quh[BATCH*HH*TT*DKK];
__device__ __half g_qvh[BATCH*HH*TT*DKK];
__device__ __half g_kh [BATCH*HH*TT*DKK];
__device__ __half g_vTh[BATCH*HH*DKK*TT];           // (b,h,d,t)
__device__ __half g_ph [HH*PP*DKK];
__device__ __half g_ath[(size_t)BATCH*HH*TT*TT];    // probs
__device__ __half g_oh [MHS*DD];
__device__ float g_scores[(size_t)BATCH*HH*TT*TT];  // 134 MB fp32

typedef const __half* hp;

// ---------------- helpers ---------------------------------------------------
__device__ __forceinline__ uint32_t cvta_s(const void* p)
{
    uint32_t a;
    asm("{ .reg .u64 t; cvta.to.shared.u64 t, %1; cvt.u32.u64 %0, t; }" : "=r"(a) : "l"(p));
    return a;
}

#define MMA_F16(D, A, B0, B1)                                              \
    asm volatile("mma.sync.aligned.m16n8k16.row.col.f32.f16.f16.f32 "      \
                 "{%0,%1,%2,%3}, {%4,%5,%6,%7}, {%8,%9}, {%0,%1,%2,%3};"   \
                 : "+f"(D[0]), "+f"(D[1]), "+f"(D[2]), "+f"(D[3])          \
                 : "r"(A[0]), "r"(A[1]), "r"(A[2]), "r"(A[3]),             \
                   "r"(B0), "r"(B1))

#define LDSM4(R, addr)                                                          \
    asm volatile("ldmatrix.sync.aligned.m8n8.x4.shared.b16 {%0,%1,%2,%3}, [%4];"\
                 : "=r"((R)[0]), "=r"((R)[1]), "=r"((R)[2]), "=r"((R)[3])       \
                 : "r"(addr))

#define CP16(dst, src, okbytes)                                            \
    asm volatile("cp.async.cg.shared.global [%0], [%1], 16, %2;"           \
                 :: "r"(dst), "l"(src), "r"(okbytes) : "memory")
#define CP_COMMIT() asm volatile("cp.async.commit_group;" ::: "memory")
#define CP_WAIT(n)  asm volatile("cp.async.wait_group %0;" :: "n"(n) : "memory")

// ---------------- generic BK-staged loader / mainloop (proj, av, out) --------
__device__ __forceinline__ void load_stage(__half* sm, int s,
    hp Ah, int M, hp Bh, int N, int K, int row0, int col0, int k0)
{
    __half* st = sm + s * STG;
    const int tid = threadIdx.x;
    #pragma unroll
    for (int t = 0; t < 2; t++) {
        int slot = tid + t * 256;
        int r = slot >> 2, seg = slot & 3;
        int g = row0 + r;
        int ok = (g < M);
        const __half* sp = Ah + (size_t)(ok ? g : 0) * K + k0 + seg * 8;
        CP16(cvta_s(st + r * ROWP + seg * 8), sp, ok ? 16 : 0);
    }
    {
        int r = tid >> 2, seg = tid & 3;
        int g = col0 + r;
        int ok = (g < N);
        const __half* sp = Bh + (size_t)(ok ? g : 0) * K + k0 + seg * 8;
        CP16(cvta_s(st + BUFA + r * ROWP + seg * 8), sp, ok ? 16 : 0);
    }
}

__device__ __forceinline__ void hmma_main(
    hp Ah, int M, hp Bh, int N,
    int K, int row0, int col0, float acc[2][4][4])
{
    extern __shared__ __half smv[];
    const int tid = threadIdx.x, lane = tid & 31, warp = tid >> 5;
    const int wm = warp >> 1, wn = warp & 1;
    const int mi = lane >> 3, lr8 = lane & 7;
    const int row_off = (mi & 1) * 8 + lr8;
    const int col_off = (mi >> 1) * 8;

    const int niter = K >> 5;
    load_stage(smv, 0, Ah, M, Bh, N, K, row0, col0, 0);
    CP_COMMIT();
    if (niter > 1) load_stage(smv, 1, Ah, M, Bh, N, K, row0, col0, 32);
    CP_COMMIT();

    for (int it = 0; it < niter; it++) {
        if (it + 2 < niter) {
            load_stage(smv, (it + 2) % STAGES, Ah, M, Bh, N, K,
                       row0, col0, (it + 2) << 5);
            CP_COMMIT();
            CP_WAIT(2);
        } else if (it + 1 < niter) {
            CP_WAIT(1);
        } else {
            CP_WAIT(0);
        }
        __syncthreads();

        const __half* st = smv + (it % STAGES) * STG;
        #pragma unroll
        for (int kb = 0; kb < BK; kb += 16) {
            uint32_t a[2][4];
            #pragma unroll
            for (int i = 0; i < 2; i++) {
                int off = (wm * 32 + i * 16 + row_off) * ROWP + kb + col_off;
                LDSM4(a[i], cvta_s(st + off));
            }
            uint32_t b4[2][4];
            #pragma unroll
            for (int g = 0; g < 2; g++) {
                int off = (wn * 32 + g * 16 + row_off) * ROWP + kb + col_off;
                LDSM4(b4[g], cvta_s(st + BUFA + off));
            }
            #pragma unroll
            for (int g = 0; g < 2; g++) {
                MMA_F16(acc[0][g*2],   a[0], b4[g][0], b4[g][2]);
                MMA_F16(acc[1][g*2],   a[1], b4[g][0], b4[g][2]);
                MMA_F16(acc[0][g*2+1], a[0], b4[g][1], b4[g][3]);
                MMA_F16(acc[1][g*2+1], a[1], b4[g][1], b4[g][3]);
            }
        }
        __syncthreads();
    }
}

// epilogue coordinate helpers (warp tile 32x32)
#define EPI_ROW(i, r)  (wm*32 + (i)*16 + grp + ((r) >> 1)*8)
#define EPI_COL(j, r)  (wn*32 + (j)*8 + qid*2 + ((r) & 1))
#define EPI_DECLS                                          \
    const int lane = threadIdx.x & 31;                     \
    const int warp = threadIdx.x >> 5;                     \
    const int grp = lane >> 2, qid = lane & 3;             \
    const int wm = warp >> 1, wn = warp & 1;

// ---------------- stream-B compute: 8 k16 chunks over resident K=128 ---------
__device__ __forceinline__ void stream_tile(const __half* sA, const __half* sBc,
                                            float acc[2][4][4])
{
    const int lane = threadIdx.x & 31, warp = threadIdx.x >> 5;
    const int wm = warp >> 1, wn = warp & 1;
    const int mi = lane >> 3, lr8 = lane & 7;
    const int row_off = (mi & 1) * 8 + lr8;
    const int col_off = (mi >> 1) * 8;
    #pragma unroll
    for (int kb = 0; kb < DKK; kb += 16) {
        uint32_t a[2][4];
        #pragma unroll
        for (int i = 0; i < 2; i++) {
            int off = (wm * 32 + i * 16 + row_off) * ROWPA + kb + col_off;
            LDSM4(a[i], cvta_s(sA + off));
        }
        uint32_t b4[2][4];
        #pragma unroll
        for (int g = 0; g < 2; g++) {
            int off = (wn * 32 + g * 16 + row_off) * ROWPA + kb + col_off;
            LDSM4(b4[g], cvta_s(sBc + off));
        }
        #pragma unroll
        for (int g = 0; g < 2; g++) {
            MMA_F16(acc[0][g*2],   a[0], b4[g][0], b4[g][2]);
            MMA_F16(acc[1][g*2],   a[1], b4[g][0], b4[g][2]);
            MMA_F16(acc[0][g*2+1], a[0], b4[g][1], b4[g][3]);
            MMA_F16(acc[1][g*2+1], a[1], b4[g][1], b4[g][3]);
        }
    }
}

__device__ __forceinline__ void stream_load_A(__half* sA, hp Ag, int row0)
{
    const int tid = threadIdx.x;
    #pragma unroll
    for (int t = 0; t < 8; t++) {
        int slot = tid + t * 256;              // 0..2047
        int r = slot >> 4, seg = slot & 15;
        const __half* sp = Ag + (size_t)(row0 + r) * DKK + seg * 8;
        CP16(cvta_s(sA + r * ROWPA + seg * 8), sp, 16);
    }
}

__device__ __forceinline__ void stream_load_B(__half* dst, hp Bg, int col0, int N)
{
    const int tid = threadIdx.x;
    #pragma unroll
    for (int t = 0; t < 4; t++) {
        int slot = tid + t * 256;              // 0..1023
        int r = slot >> 4, seg = slot & 15;
        int g = col0 + r;
        int ok = (g < N);
        const __half* sp = Bg + (size_t)(ok ? g : 0) * DKK + seg * 8;
        CP16(cvta_s(dst + r * ROWPA + seg * 8), sp, ok ? 16 : 0);
    }
}

// ---------------- splits (fp16 convert only) ---------------------------------
__global__ void k_split_hs(const float* __restrict__ hs)
{
    int i = blockIdx.x * blockDim.x + threadIdx.x;
    if (i < MHS*DD) g_hsh[i] = __float2half_rn(hs[i]);
}

__global__ void k_split_pe(const float* __restrict__ pe)
{
    int i = blockIdx.x * blockDim.x + threadIdx.x;
    if (i < PE_N) g_peh[i] = __float2half_rn(pe[i]);
}

__global__ void k_split_w(const float* __restrict__ Wq,
                          const float* __restrict__ Wk,
                          const float* __restrict__ Wv,
                          const float* __restrict__ Wo,
                          const float* __restrict__ Wp)
{
    int i = blockIdx.x * blockDim.x + threadIdx.x;
    if (i >= 5 * DD * DD) return;
    int w = i >> 20, o = i & (DD*DD - 1);
    const float* src = (w == 0) ? Wq : (w == 1) ? Wk : (w == 2) ? Wv
                     : (w == 3) ? Wo : Wp;
    __half* dst = (w == 0) ? g_Wqh : (w == 1) ? g_Wkh : (w == 2) ? g_Wvh
                : (w == 3) ? g_Woh : g_Wph;
    dst[o] = __float2half_rn(src[o]);
}

// ---------------- Q / K / P / V projections, single launch -------------------
__global__ void __launch_bounds__(256, 3)
k_proj(const float* __restrict__ bu, const float* __restrict__ bv)
{
    const int z = blockIdx.z;                     // 0:Q 1:K 2:P 3:V
    if (z == 2 && blockIdx.y >= 16) return;       // P has 16 row tiles
    hp Ah = (z == 2) ? g_peh : g_hsh;
    const int M = (z == 2) ? PP : MHS;
    hp Wh = (z == 0) ? g_Wqh : (z == 1) ? g_Wkh : (z == 2) ? g_Wph : g_Wvh;
    const int row0 = blockIdx.y * 128, col0 = blockIdx.x * 64;
    float acc[2][4][4] = {};
    hmma_main(Ah, M, Wh, DD, DD, row0, col0, acc);
    EPI_DECLS
    #pragma unroll
    for (int i = 0; i < 2; i++)
        #pragma unroll
        for (int j = 0; j < 4; j++)
            #pragma unroll
            for (int r = 0; r < 4; r++) {
                int m = row0 + EPI_ROW(i, r);
                int n = col0 + EPI_COL(j, r);
                int h = n >> 7, d = n & 127;
                float v = acc[i][j][r];
                if (z == 0) {
                    int b = m >> 10, t = m & 1023;
                    size_t idx = ((size_t)(b*HH + h)*TT + t)*DKK + d;
                    g_quh[idx] = __float2half_rn(v + bu[h*DKK + d]);
                    g_qvh[idx] = __float2half_rn(v + bv[h*DKK + d]);
                } else if (z == 1) {
                    int b = m >> 10, t = m & 1023;
                    size_t idx = ((size_t)(b*HH + h)*TT + t)*DKK + d;
                    g_kh[idx] = __float2half_rn(v);
                } else if (z == 2) {
                    if (m < PP) {
                        size_t idx = ((size_t)h*PP + m)*DKK + d;
                        g_ph[idx] = __float2half_rn(v);
                    }
                } else {
                    int b = m >> 10, t = m & 1023;
                    size_t it = ((size_t)(b*HH + h)*DKK + d)*TT + t;  // (b,h,d,t)
                    g_vTh[it] = __float2half_rn(v);
                }
            }
}

// ---------------- AC (stream-B): scores = qu @ k^T per (b,h) -----------------
__global__ void __launch_bounds__(256, 2) k_ac()
{
    extern __shared__ __half sm[];
    __half* sA = sm;
    __half* sB = sm + SA_HAL;                     // 2 buffers of SB_HAL
    const int bh = blockIdx.y;
    const int row0 = blockIdx.x * 128;
    const size_t ob = (size_t)bh * TT * DKK;
    hp Ag = g_quh + ob;
    hp Bg = g_kh + ob;

    stream_load_A(sA, Ag, row0);
    CP_COMMIT();
    stream_load_B(sB, Bg, 0, TT);
    CP_COMMIT();

    float* C = g_scores + (size_t)bh * TT * TT;
    EPI_DECLS
    for (int cx = 0; cx < 16; cx++) {
        if (cx + 1 < 16) {
            stream_load_B(sB + ((cx + 1) & 1) * SB_HAL, Bg, (cx + 1) * 64, TT);
            CP_COMMIT();
            CP_WAIT(1);
        } else {
            CP_WAIT(0);
        }
        __syncthreads();
        const __half* sBc = sB + (cx & 1) * SB_HAL;
        float acc[2][4][4] = {};
        stream_tile(sA, sBc, acc);
        __syncthreads();
        const int col0 = cx * 64;
        #pragma unroll
        for (int i = 0; i < 2; i++)
            #pragma unroll
            for (int j = 0; j < 4; j++)
                #pragma unroll
                for (int r = 0; r < 4; r++) {
                    int m = row0 + EPI_ROW(i, r);
                    int n = col0 + EPI_COL(j, r);
                    C[(size_t)m * TT + n] = acc[i][j][r];
                }
    }
}

// ---------------- BD (stream-B): scores[m, n+m-1023] += qv @ p^T -------------
// band of 18 col-tiles per row-tile: cx = cxmin..cxmin+17
__global__ void __launch_bounds__(256, 2) k_bd()
{
    extern __shared__ __half sm[];
    __half* sA = sm;
    __half* sB = sm + SA_HAL;
    const int bh = blockIdx.y, h = bh & 7;
    const int my = blockIdx.x;
    const int row0 = my * 128;
    int cxmin = 896 - 128 * my;
    cxmin = (cxmin > 0) ? (cxmin >> 6) : 0;
    const size_t oa = (size_t)bh * TT * DKK;
    const size_t op = (size_t)h * PP * DKK;
    hp Ag = g_qvh + oa;
    hp Bg = g_ph + op;

    stream_load_A(sA, Ag, row0);
    CP_COMMIT();
    stream_load_B(sB, Bg, cxmin * 64, PP);
    CP_COMMIT();

    float* C = g_scores + (size_t)bh * TT * TT;
    EPI_DECLS
    for (int i2 = 0; i2 < 18; i2++) {
        if (i2 + 1 < 18) {
            stream_load_B(sB + ((i2 + 1) & 1) * SB_HAL, Bg,
                          (cxmin + i2 + 1) * 64, PP);
            CP_COMMIT();
            CP_WAIT(1);
        } else {
            CP_WAIT(0);
        }
        __syncthreads();
        const __half* sBc = sB + (i2 & 1) * SB_HAL;
        float acc[2][4][4] = {};
        stream_tile(sA, sBc, acc);
        __syncthreads();
        const int col0 = (cxmin + i2) * 64;
        #pragma unroll
        for (int i = 0; i < 2; i++)
            #pragma unroll
            for (int j = 0; j < 4; j++)
                #pragma unroll
                for (int r = 0; r < 4; r++) {
                    int m = row0 + EPI_ROW(i, r);
                    int n = col0 + EPI_COL(j, r);
                    if (n < PP) {
                        int k = n + m - 1023;
                        if ((unsigned)k < (unsigned)TT)
                            C[(size_t)m * TT + k] += acc[i][j][r];
                    }
                }
    }
}

// ---------------- softmax: warp-per-row, shuffle-only reductions -------------
__global__ void k_softmax()
{
    const int row  = blockIdx.x * 8 + (threadIdx.x >> 5);
    const int lane = threadIdx.x & 31;
    const size_t rowoff = (size_t)row * TT;
    const float4* r4 = reinterpret_cast<const float4*>(g_scores + rowoff);
    const float s = 0.08838834764831845f;        // 1/sqrt(128)

    float4 v[8];
    float m = -1e30f;
    #pragma unroll
    for (int i = 0; i < 8; i++) {
        v[i] = r4[i * 32 + lane];
        v[i].x *= s; v[i].y *= s; v[i].z *= s; v[i].w *= s;
        m = fmaxf(m, fmaxf(fmaxf(v[i].x, v[i].y), fmaxf(v[i].z, v[i].w)));
    }
    #pragma unroll
    for (int o = 16; o > 0; o >>= 1) m = fmaxf(m, __shfl_xor_sync(~0u, m, o));

    float sum = 0.f;
    #pragma unroll
    for (int i = 0; i < 8; i++) {
        v[i].x = __expf(v[i].x - m); v[i].y = __expf(v[i].y - m);
        v[i].z = __expf(v[i].z - m); v[i].w = __expf(v[i].w - m);
        sum += (v[i].x + v[i].y) + (v[i].z + v[i].w);
    }
    #pragma unroll
    for (int o = 16; o > 0; o >>= 1) sum += __shfl_xor_sync(~0u, sum, o);

    float inv = __frcp_rn(sum);
    uint2* dst = reinterpret_cast<uint2*>(g_ath + rowoff);
    #pragma unroll
    for (int i = 0; i < 8; i++) {
        __half2 p01 = __floats2half2_rn(v[i].x * inv, v[i].y * inv);
        __half2 p23 = __floats2half2_rn(v[i].z * inv, v[i].w * inv);
        uint2 pk;
        pk.x = *reinterpret_cast<uint32_t*>(&p01);
        pk.y = *reinterpret_cast<uint32_t*>(&p23);
        dst[i * 32 + lane] = pk;
    }
}

// ---------------- AV: o = attn @ v per (b,h) --------------------------------
__global__ void __launch_bounds__(256, 3) k_av()
{
    const int bh = blockIdx.z, b = bh >> 3, h = bh & 7;
    const size_t oa = (size_t)bh * TT * TT;
    const size_t ov = (size_t)bh * DKK * TT;
    const int row0 = blockIdx.y * 128, col0 = blockIdx.x * 64;
    float acc[2][4][4] = {};
    hmma_main(g_ath + oa, TT, g_vTh + ov, DKK, TT, row0, col0, acc);
    EPI_DECLS
    #pragma unroll
    for (int i = 0; i < 2; i++)
        #pragma unroll
        for (int j = 0; j < 4; j++)
            #pragma unroll
            for (int r = 0; r < 4; r++) {
                int m = row0 + EPI_ROW(i, r);
                int n = col0 + EPI_COL(j, r);       // head-dim 0..127
                size_t idx = ((size_t)(b*TT + m)*HH + h)*DKK + n; // (b,t,h,d)
                g_oh[idx] = __float2half_rn(acc[i][j][r]);
            }
}

// ---------------- output projection ------------------------------------------
__global__ void __launch_bounds__(256, 3) k_out(float* __restrict__ out)
{
    const int row0 = blockIdx.y * 128, col0 = blockIdx.x * 64;
    float acc[2][4][4] = {};
    hmma_main(g_oh, MHS, g_Woh, DD, DD, row0, col0, acc);
    EPI_DECLS
    #pragma unroll
    for (int i = 0; i < 2; i++)
        #pragma unroll
        for (int j = 0; j < 4; j++)
            #pragma unroll
            for (int r = 0; r < 4; r++) {
                int m = row0 + EPI_ROW(i, r);
                int n = col0 + EPI_COL(j, r);
                out[(size_t)m * DD + n] = acc[i][j][r];
            }
}

// ---------------- launch ----------------------------------------------------
extern "C" void kernel_launch(void* const* d_in, const int* in_sizes, int n_in,
                              void* d_out, int out_size)
{
    const float* hs = (const float*)d_in[0];
    const float* pe = (const float*)d_in[1];
    const float* Wq = (const float*)d_in[2];
    const float* Wk = (const float*)d_in[3];
    const float* Wv = (const float*)d_in[4];
    const float* Wo = (const float*)d_in[5];
    const float* Wp = (const float*)d_in[6];
    const float* bu = (const float*)d_in[7];
    const float* bv = (const float*)d_in[8];
    float* out = (float*)d_out;

    static int attr_done = 0;
    if (!attr_done) {
        cudaFuncSetAttribute(k_proj, cudaFuncAttributeMaxDynamicSharedMemorySize, DYN);
        cudaFuncSetAttribute(k_ac,   cudaFuncAttributeMaxDynamicSharedMemorySize, DYNS);
        cudaFuncSetAttribute(k_bd,   cudaFuncAttributeMaxDynamicSharedMemorySize, DYNS);
        cudaFuncSetAttribute(k_av,   cudaFuncAttributeMaxDynamicSharedMemorySize, DYN);
        cudaFuncSetAttribute(k_out,  cudaFuncAttributeMaxDynamicSharedMemorySize, DYN);
        attr_done = 1;
    }

    // launch order keeps k_bd at position 6 so ncu (-s 5 -c 1) profiles it
    k_split_hs<<<(MHS*DD + 255)/256, 256>>>(hs);
    k_split_pe<<<(PE_N + 255)/256, 256>>>(pe);
    k_split_w <<<(5*DD*DD + 255)/256, 256>>>(Wq, Wk, Wv, Wo, Wp);

    k_proj<<<dim3(16, 32, 4), 256, DYN>>>(bu, bv);
    k_ac <<<dim3(8, 32), 256, DYNS>>>();
    k_bd <<<dim3(8, 32), 256, DYNS>>>();
    k_softmax<<<BATCH*HH*TT/8, 256>>>();
    k_av <<<dim3(2, 8, BATCH*HH), 256, DYN>>>();
    k_out<<<dim3(16, 32), 256, DYN>>>(out);
}

// round 15
// speedup vs baseline: 1.1409x; 1.1409x over previous
#include <cuda_runtime.h>
#include <cuda_fp16.h>
#include <stdint.h>

#define BATCH 4
#define TT    1024
#define DD    1024
#define HH    8
#define DKK   128
#define PP    2047
#define MHS   (BATCH*TT)
#define BK    32
#define ROWP  40                        // padded smem row stride (halves)
#define BUFA  (128*ROWP)                // A buffer: 128 rows
#define BUFB  (64*ROWP)                 // B buffer: 64 rows
#define STAGES 3
#define STG   (BUFA + BUFB)             // halves per stage
#define DYN   (STAGES*STG*2)            // 46080 B  (K-streamed kernels)
#define DYN4  (4*STG*2)                 // 61440 B  (K=128 full-prefetch kernels)
#define PE_N  (PP*DD)

// ---------------- scratch (device globals; all one-term fp16) ----------------
__device__ __half g_hsh[MHS*DD];
__device__ __half g_peh[PE_N];
__device__ __half g_Wqh[DD*DD], g_Wkh[DD*DD], g_Wvh[DD*DD];
__device__ __half g_Woh[DD*DD], g_Wph[DD*DD];
__device__ __half g_quh[BATCH*HH*TT*DKK];
__device__ __half g_qvh[BATCH*HH*TT*DKK];
__device__ __half g_kh [BATCH*HH*TT*DKK];
__device__ __half g_vTh[BATCH*HH*DKK*TT];           // (b,h,d,t)
__device__ __half g_ph [HH*PP*DKK];
__device__ __half g_ath[(size_t)BATCH*HH*TT*TT];    // probs
__device__ __half g_oh [MHS*DD];
__device__ float g_scores[(size_t)BATCH*HH*TT*TT];  // 134 MB fp32

typedef const __half* hp;

// ---------------- helpers ---------------------------------------------------
__device__ __forceinline__ uint32_t cvta_s(const void* p)
{
    uint32_t a;
    asm("{ .reg .u64 t; cvta.to.shared.u64 t, %1; cvt.u32.u64 %0, t; }" : "=r"(a) : "l"(p));
    return a;
}

#define MMA_F16(D, A, B0, B1)                                              \
    asm volatile("mma.sync.aligned.m16n8k16.row.col.f32.f16.f16.f32 "      \
                 "{%0,%1,%2,%3}, {%4,%5,%6,%7}, {%8,%9}, {%0,%1,%2,%3};"   \
                 : "+f"(D[0]), "+f"(D[1]), "+f"(D[2]), "+f"(D[3])          \
                 : "r"(A[0]), "r"(A[1]), "r"(A[2]), "r"(A[3]),             \
                   "r"(B0), "r"(B1))

#define LDSM4(R, addr)                                                          \
    asm volatile("ldmatrix.sync.aligned.m8n8.x4.shared.b16 {%0,%1,%2,%3}, [%4];"\
                 : "=r"((R)[0]), "=r"((R)[1]), "=r"((R)[2]), "=r"((R)[3])       \
                 : "r"(addr))

#define CP16(dst, src, okbytes)                                            \
    asm volatile("cp.async.cg.shared.global [%0], [%1], 16, %2;"           \
                 :: "r"(dst), "l"(src), "r"(okbytes) : "memory")
#define CP_COMMIT() asm volatile("cp.async.commit_group;" ::: "memory")
#define CP_WAIT(n)  asm volatile("cp.async.wait_group %0;" :: "n"(n) : "memory")

// ---------------- stage loader (BK=32 chunk) ---------------------------------
__device__ __forceinline__ void load_stage(__half* sm, int s,
    hp Ah, int M, hp Bh, int N, int K, int row0, int col0, int k0)
{
    __half* st = sm + s * STG;
    const int tid = threadIdx.x;
    #pragma unroll
    for (int t = 0; t < 2; t++) {
        int slot = tid + t * 256;
        int r = slot >> 2, seg = slot & 3;
        int g = row0 + r;
        int ok = (g < M);
        const __half* sp = Ah + (size_t)(ok ? g : 0) * K + k0 + seg * 8;
        CP16(cvta_s(st + r * ROWP + seg * 8), sp, ok ? 16 : 0);
    }
    {
        int r = tid >> 2, seg = tid & 3;
        int g = col0 + r;
        int ok = (g < N);
        const __half* sp = Bh + (size_t)(ok ? g : 0) * K + k0 + seg * 8;
        CP16(cvta_s(st + BUFA + r * ROWP + seg * 8), sp, ok ? 16 : 0);
    }
}

// ---------------- one BK=32 compute chunk ------------------------------------
__device__ __forceinline__ void mma_chunk(const __half* st, int wm, int wn,
                                          int row_off, int col_off,
                                          float acc[2][4][4])
{
    #pragma unroll
    for (int kb = 0; kb < BK; kb += 16) {
        uint32_t a[2][4];
        #pragma unroll
        for (int i = 0; i < 2; i++) {
            int off = (wm * 32 + i * 16 + row_off) * ROWP + kb + col_off;
            LDSM4(a[i], cvta_s(st + off));
        }
        uint32_t b4[2][4];
        #pragma unroll
        for (int g = 0; g < 2; g++) {
            int off = (wn * 32 + g * 16 + row_off) * ROWP + kb + col_off;
            LDSM4(b4[g], cvta_s(st + BUFA + off));
        }
        #pragma unroll
        for (int g = 0; g < 2; g++) {
            MMA_F16(acc[0][g*2],   a[0], b4[g][0], b4[g][2]);
            MMA_F16(acc[1][g*2],   a[1], b4[g][0], b4[g][2]);
            MMA_F16(acc[0][g*2+1], a[0], b4[g][1], b4[g][3]);
            MMA_F16(acc[1][g*2+1], a[1], b4[g][1], b4[g][3]);
        }
    }
}

#define FRAG_DECLS                                         \
    const int lane = threadIdx.x & 31;                     \
    const int warp = threadIdx.x >> 5;                     \
    const int wm = warp >> 1, wn = warp & 1;               \
    const int mi = lane >> 3, lr8 = lane & 7;              \
    const int row_off = (mi & 1) * 8 + lr8;                \
    const int col_off = (mi >> 1) * 8;

// ---------------- generic K-streamed mainloop (proj, av, out) ----------------
__device__ __forceinline__ void hmma_main(
    hp Ah, int M, hp Bh, int N,
    int K, int row0, int col0, float acc[2][4][4])
{
    extern __shared__ __half smv[];
    FRAG_DECLS

    const int niter = K >> 5;
    load_stage(smv, 0, Ah, M, Bh, N, K, row0, col0, 0);
    CP_COMMIT();
    if (niter > 1) load_stage(smv, 1, Ah, M, Bh, N, K, row0, col0, 32);
    CP_COMMIT();

    for (int it = 0; it < niter; it++) {
        if (it + 2 < niter) {
            load_stage(smv, (it + 2) % STAGES, Ah, M, Bh, N, K,
                       row0, col0, (it + 2) << 5);
            CP_COMMIT();
            CP_WAIT(2);
        } else if (it + 1 < niter) {
            CP_WAIT(1);
        } else {
            CP_WAIT(0);
        }
        __syncthreads();
        mma_chunk(smv + (it % STAGES) * STG, wm, wn, row_off, col_off, acc);
        __syncthreads();
    }
}

// ---------------- K=128 full-prefetch mainloop (ac, bd) ----------------------
// 4 stages loaded up-front (one commit group each); no stage reuse, no recycle
// stalls; compute chunk i gated only by wait_group(3-i).
__device__ __forceinline__ void hmma_k128(
    hp Ah, int M, hp Bh, int N, int row0, int col0, float acc[2][4][4])
{
    extern __shared__ __half smv[];
    FRAG_DECLS

    load_stage(smv, 0, Ah, M, Bh, N, DKK, row0, col0, 0);   CP_COMMIT();
    load_stage(smv, 1, Ah, M, Bh, N, DKK, row0, col0, 32);  CP_COMMIT();
    load_stage(smv, 2, Ah, M, Bh, N, DKK, row0, col0, 64);  CP_COMMIT();
    load_stage(smv, 3, Ah, M, Bh, N, DKK, row0, col0, 96);  CP_COMMIT();

    CP_WAIT(3); __syncthreads();
    mma_chunk(smv + 0 * STG, wm, wn, row_off, col_off, acc);
    CP_WAIT(2); __syncthreads();
    mma_chunk(smv + 1 * STG, wm, wn, row_off, col_off, acc);
    CP_WAIT(1); __syncthreads();
    mma_chunk(smv + 2 * STG, wm, wn, row_off, col_off, acc);
    CP_WAIT(0); __syncthreads();
    mma_chunk(smv + 3 * STG, wm, wn, row_off, col_off, acc);
}

// epilogue coordinate helpers (warp tile 32x32)
#define EPI_ROW(i, r)  (wm*32 + (i)*16 + grp + ((r) >> 1)*8)
#define EPI_COL(j, r)  (wn*32 + (j)*8 + qid*2 + ((r) & 1))
#define EPI_DECLS                                          \
    const int lane = threadIdx.x & 31;                     \
    const int warp = threadIdx.x >> 5;                     \
    const int grp = lane >> 2, qid = lane & 3;             \
    const int wm = warp >> 1, wn = warp & 1;

// ---------------- splits (fp16 convert only) ---------------------------------
__global__ void k_split_hs(const float* __restrict__ hs)
{
    int i = blockIdx.x * blockDim.x + threadIdx.x;
    if (i < MHS*DD) g_hsh[i] = __float2half_rn(hs[i]);
}

__global__ void k_split_pe(const float* __restrict__ pe)
{
    int i = blockIdx.x * blockDim.x + threadIdx.x;
    if (i < PE_N) g_peh[i] = __float2half_rn(pe[i]);
}

__global__ void k_split_w(const float* __restrict__ Wq,
                          const float* __restrict__ Wk,
                          const float* __restrict__ Wv,
                          const float* __restrict__ Wo,
                          const float* __restrict__ Wp)
{
    int i = blockIdx.x * blockDim.x + threadIdx.x;
    if (i >= 5 * DD * DD) return;
    int w = i >> 20, o = i & (DD*DD - 1);
    const float* src = (w == 0) ? Wq : (w == 1) ? Wk : (w == 2) ? Wv
                     : (w == 3) ? Wo : Wp;
    __half* dst = (w == 0) ? g_Wqh : (w == 1) ? g_Wkh : (w == 2) ? g_Wvh
                : (w == 3) ? g_Woh : g_Wph;
    dst[o] = __float2half_rn(src[o]);
}

// ---------------- Q / K / P / V projections, single launch -------------------
__global__ void __launch_bounds__(256, 3)
k_proj(const float* __restrict__ bu, const float* __restrict__ bv)
{
    const int z = blockIdx.z;                     // 0:Q 1:K 2:P 3:V
    if (z == 2 && blockIdx.y >= 16) return;       // P has 16 row tiles
    hp Ah = (z == 2) ? g_peh : g_hsh;
    const int M = (z == 2) ? PP : MHS;
    hp Wh = (z == 0) ? g_Wqh : (z == 1) ? g_Wkh : (z == 2) ? g_Wph : g_Wvh;
    const int row0 = blockIdx.y * 128, col0 = blockIdx.x * 64;
    float acc[2][4][4] = {};
    hmma_main(Ah, M, Wh, DD, DD, row0, col0, acc);
    EPI_DECLS
    #pragma unroll
    for (int i = 0; i < 2; i++)
        #pragma unroll
        for (int j = 0; j < 4; j++)
            #pragma unroll
            for (int r = 0; r < 4; r++) {
                int m = row0 + EPI_ROW(i, r);
                int n = col0 + EPI_COL(j, r);
                int h = n >> 7, d = n & 127;
                float v = acc[i][j][r];
                if (z == 0) {
                    int b = m >> 10, t = m & 1023;
                    size_t idx = ((size_t)(b*HH + h)*TT + t)*DKK + d;
                    g_quh[idx] = __float2half_rn(v + bu[h*DKK + d]);
                    g_qvh[idx] = __float2half_rn(v + bv[h*DKK + d]);
                } else if (z == 1) {
                    int b = m >> 10, t = m & 1023;
                    size_t idx = ((size_t)(b*HH + h)*TT + t)*DKK + d;
                    g_kh[idx] = __float2half_rn(v);
                } else if (z == 2) {
                    if (m < PP) {
                        size_t idx = ((size_t)h*PP + m)*DKK + d;
                        g_ph[idx] = __float2half_rn(v);
                    }
                } else {
                    int b = m >> 10, t = m & 1023;
                    size_t it = ((size_t)(b*HH + h)*DKK + d)*TT + t;  // (b,h,d,t)
                    g_vTh[it] = __float2half_rn(v);
                }
            }
}

// ---------------- AC: scores = qu @ k^T per (b,h)  (K=128 full-prefetch) -----
__global__ void __launch_bounds__(256, 3) k_ac()
{
    const int bh = blockIdx.z;
    const size_t ob = (size_t)bh * TT * DKK;
    const int row0 = blockIdx.y * 128, col0 = blockIdx.x * 64;
    float acc[2][4][4] = {};
    hmma_k128(g_quh + ob, TT, g_kh + ob, TT, row0, col0, acc);
    EPI_DECLS
    float* C = g_scores + (size_t)bh * TT * TT;
    #pragma unroll
    for (int i = 0; i < 2; i++)
        #pragma unroll
        for (int j = 0; j < 4; j++)
            #pragma unroll
            for (int r = 0; r < 4; r++) {
                int m = row0 + EPI_ROW(i, r);
                int n = col0 + EPI_COL(j, r);
                C[(size_t)m * TT + n] = acc[i][j][r];
            }
}

// ---------------- BD: scores[m, n+m-1023] += qv @ p^T (rel-shift fused) ------
// exact diagonal band for 64-wide col tiles: 18 tiles per row tile
__global__ void __launch_bounds__(256, 3) k_bd()
{
    const int bh = blockIdx.z, h = bh & 7;
    const int my = blockIdx.y;
    int cxmin = 896 - 128 * my;
    cxmin = (cxmin > 0) ? (cxmin >> 6) : 0;
    const int cx = blockIdx.x + cxmin;
    const int row0 = my * 128, col0 = cx * 64;
    const size_t oa = (size_t)bh * TT * DKK;
    const size_t op = (size_t)h * PP * DKK;
    float acc[2][4][4] = {};
    hmma_k128(g_qvh + oa, TT, g_ph + op, PP, row0, col0, acc);
    EPI_DECLS
    float* C = g_scores + (size_t)bh * TT * TT;
    #pragma unroll
    for (int i = 0; i < 2; i++)
        #pragma unroll
        for (int j = 0; j < 4; j++)
            #pragma unroll
            for (int r = 0; r < 4; r++) {
                int m = row0 + EPI_ROW(i, r);
                int n = col0 + EPI_COL(j, r);
                if (n < PP) {
                    int k = n + m - 1023;
                    if ((unsigned)k < (unsigned)TT)
                        C[(size_t)m * TT + k] += acc[i][j][r];
                }
            }
}

// ---------------- softmax: warp-per-row, shuffle-only reductions -------------
__global__ void k_softmax()
{
    const int row  = blockIdx.x * 8 + (threadIdx.x >> 5);
    const int lane = threadIdx.x & 31;
    const size_t rowoff = (size_t)row * TT;
    const float4* r4 = reinterpret_cast<const float4*>(g_scores + rowoff);
    const float s = 0.08838834764831845f;        // 1/sqrt(128)

    float4 v[8];
    float m = -1e30f;
    #pragma unroll
    for (int i = 0; i < 8; i++) {
        v[i] = r4[i * 32 + lane];
        v[i].x *= s; v[i].y *= s; v[i].z *= s; v[i].w *= s;
        m = fmaxf(m, fmaxf(fmaxf(v[i].x, v[i].y), fmaxf(v[i].z, v[i].w)));
    }
    #pragma unroll
    for (int o = 16; o > 0; o >>= 1) m = fmaxf(m, __shfl_xor_sync(~0u, m, o));

    float sum = 0.f;
    #pragma unroll
    for (int i = 0; i < 8; i++) {
        v[i].x = __expf(v[i].x - m); v[i].y = __expf(v[i].y - m);
        v[i].z = __expf(v[i].z - m); v[i].w = __expf(v[i].w - m);
        sum += (v[i].x + v[i].y) + (v[i].z + v[i].w);
    }
    #pragma unroll
    for (int o = 16; o > 0; o >>= 1) sum += __shfl_xor_sync(~0u, sum, o);

    float inv = __frcp_rn(sum);
    uint2* dst = reinterpret_cast<uint2*>(g_ath + rowoff);
    #pragma unroll
    for (int i = 0; i < 8; i++) {
        __half2 p01 = __floats2half2_rn(v[i].x * inv, v[i].y * inv);
        __half2 p23 = __floats2half2_rn(v[i].z * inv, v[i].w * inv);
        uint2 pk;
        pk.x = *reinterpret_cast<uint32_t*>(&p01);
        pk.y = *reinterpret_cast<uint32_t*>(&p23);
        dst[i * 32 + lane] = pk;
    }
}

// ---------------- AV: o = attn @ v per (b,h) --------------------------------
__global__ void __launch_bounds__(256, 3) k_av()
{
    const int bh = blockIdx.z, b = bh >> 3, h = bh & 7;
    const size_t oa = (size_t)bh * TT * TT;
    const size_t ov = (size_t)bh * DKK * TT;
    const int row0 = blockIdx.y * 128, col0 = blockIdx.x * 64;
    float acc[2][4][4] = {};
    hmma_main(g_ath + oa, TT, g_vTh + ov, DKK, TT, row0, col0, acc);
    EPI_DECLS
    #pragma unroll
    for (int i = 0; i < 2; i++)
        #pragma unroll
        for (int j = 0; j < 4; j++)
            #pragma unroll
            for (int r = 0; r < 4; r++) {
                int m = row0 + EPI_ROW(i, r);
                int n = col0 + EPI_COL(j, r);       // head-dim 0..127
                size_t idx = ((size_t)(b*TT + m)*HH + h)*DKK + n; // (b,t,h,d)
                g_oh[idx] = __float2half_rn(acc[i][j][r]);
            }
}

// ---------------- output projection ------------------------------------------
__global__ void __launch_bounds__(256, 3) k_out(float* __restrict__ out)
{
    const int row0 = blockIdx.y * 128, col0 = blockIdx.x * 64;
    float acc[2][4][4] = {};
    hmma_main(g_oh, MHS, g_Woh, DD, DD, row0, col0, acc);
    EPI_DECLS
    #pragma unroll
    for (int i = 0; i < 2; i++)
        #pragma unroll
        for (int j = 0; j < 4; j++)
            #pragma unroll
            for (int r = 0; r < 4; r++) {
                int m = row0 + EPI_ROW(i, r);
                int n = col0 + EPI_COL(j, r);
                out[(size_t)m * DD + n] = acc[i][j][r];
            }
}

// ---------------- launch ----------------------------------------------------
extern "C" void kernel_launch(void* const* d_in, const int* in_sizes, int n_in,
                              void* d_out, int out_size)
{
    const float* hs = (const float*)d_in[0];
    const float* pe = (const float*)d_in[1];
    const float* Wq = (const float*)d_in[2];
    const float* Wk = (const float*)d_in[3];
    const float* Wv = (const float*)d_in[4];
    const float* Wo = (const float*)d_in[5];
    const float* Wp = (const float*)d_in[6];
    const float* bu = (const float*)d_in[7];
    const float* bv = (const float*)d_in[8];
    float* out = (float*)d_out;

    static int attr_done = 0;
    if (!attr_done) {
        cudaFuncSetAttribute(k_proj, cudaFuncAttributeMaxDynamicSharedMemorySize, DYN);
        cudaFuncSetAttribute(k_ac,   cudaFuncAttributeMaxDynamicSharedMemorySize, DYN4);
        cudaFuncSetAttribute(k_bd,   cudaFuncAttributeMaxDynamicSharedMemorySize, DYN4);
        cudaFuncSetAttribute(k_av,   cudaFuncAttributeMaxDynamicSharedMemorySize, DYN);
        cudaFuncSetAttribute(k_out,  cudaFuncAttributeMaxDynamicSharedMemorySize, DYN);
        attr_done = 1;
    }

    k_split_hs<<<(MHS*DD + 255)/256, 256>>>(hs);
    k_split_pe<<<(PE_N + 255)/256, 256>>>(pe);
    k_split_w <<<(5*DD*DD + 255)/256, 256>>>(Wq, Wk, Wv, Wo, Wp);

    k_proj<<<dim3(16, 32, 4), 256, DYN>>>(bu, bv);
    k_ac <<<dim3(16, 8, BATCH*HH), 256, DYN4>>>();
    k_bd <<<dim3(18, 8, BATCH*HH), 256, DYN4>>>();
    k_softmax<<<BATCH*HH*TT/8, 256>>>();
    k_av <<<dim3(2, 8, BATCH*HH), 256, DYN>>>();
    k_out<<<dim3(16, 32), 256, DYN>>>(out);
}

// round 16
// speedup vs baseline: 1.1560x; 1.0133x over previous
#include <cuda_runtime.h>
#include <cuda_fp16.h>
#include <stdint.h>

#define BATCH 4
#define TT    1024
#define DD    1024
#define HH    8
#define DKK   128
#define PP    2047
#define MHS   (BATCH*TT)
#define BK    32
#define ROWP  40                        // padded smem row stride (halves)
#define BUFA  (128*ROWP)                // 128-row buffer
#define BUFB  (64*ROWP)                 // 64-row buffer
#define STAGES 3
#define STG   (BUFA + BUFB)             // stage: A128 + B64
#define STGW  (2*BUFA)                  // stage: A128 + B128 (wide kernels)
#define DYN   (STAGES*STG*2)            // 46080 B
#define DYN4  (4*STG*2)                 // 61440 B
#define DYNW  (STAGES*STGW*2)           // 61440 B
#define PE_N  (PP*DD)

// ---------------- scratch (device globals; all one-term fp16) ----------------
__device__ __half g_hsh[MHS*DD];
__device__ __half g_peh[PE_N];
__device__ __half g_Wqh[DD*DD], g_Wkh[DD*DD], g_Wvh[DD*DD];
__device__ __half g_Woh[DD*DD], g_Wph[DD*DD];
__device__ __half g_quh[BATCH*HH*TT*DKK];
__device__ __half g_qvh[BATCH*HH*TT*DKK];
__device__ __half g_kh [BATCH*HH*TT*DKK];
__device__ __half g_vTh[BATCH*HH*DKK*TT];           // (b,h,d,t)
__device__ __half g_ph [HH*PP*DKK];
__device__ __half g_ath[(size_t)BATCH*HH*TT*TT];    // probs
__device__ __half g_oh [MHS*DD];
__device__ float g_scores[(size_t)BATCH*HH*TT*TT];  // 134 MB fp32

typedef const __half* hp;

// ---------------- helpers ---------------------------------------------------
__device__ __forceinline__ uint32_t cvta_s(const void* p)
{
    uint32_t a;
    asm("{ .reg .u64 t; cvta.to.shared.u64 t, %1; cvt.u32.u64 %0, t; }" : "=r"(a) : "l"(p));
    return a;
}

#define MMA_F16(D, A, B0, B1)                                              \
    asm volatile("mma.sync.aligned.m16n8k16.row.col.f32.f16.f16.f32 "      \
                 "{%0,%1,%2,%3}, {%4,%5,%6,%7}, {%8,%9}, {%0,%1,%2,%3};"   \
                 : "+f"(D[0]), "+f"(D[1]), "+f"(D[2]), "+f"(D[3])          \
                 : "r"(A[0]), "r"(A[1]), "r"(A[2]), "r"(A[3]),             \
                   "r"(B0), "r"(B1))

#define LDSM4(R, addr)                                                          \
    asm volatile("ldmatrix.sync.aligned.m8n8.x4.shared.b16 {%0,%1,%2,%3}, [%4];"\
                 : "=r"((R)[0]), "=r"((R)[1]), "=r"((R)[2]), "=r"((R)[3])       \
                 : "r"(addr))

#define CP16(dst, src, okbytes)                                            \
    asm volatile("cp.async.cg.shared.global [%0], [%1], 16, %2;"           \
                 :: "r"(dst), "l"(src), "r"(okbytes) : "memory")
#define CP_COMMIT() asm volatile("cp.async.commit_group;" ::: "memory")
#define CP_WAIT(n)  asm volatile("cp.async.wait_group %0;" :: "n"(n) : "memory")

// ---------------- stage loaders ----------------------------------------------
__device__ __forceinline__ void load_stage(__half* sm, int s,
    hp Ah, int M, hp Bh, int N, int K, int row0, int col0, int k0)
{
    __half* st = sm + s * STG;
    const int tid = threadIdx.x;
    #pragma unroll
    for (int t = 0; t < 2; t++) {
        int slot = tid + t * 256;
        int r = slot >> 2, seg = slot & 3;
        int g = row0 + r;
        int ok = (g < M);
        const __half* sp = Ah + (size_t)(ok ? g : 0) * K + k0 + seg * 8;
        CP16(cvta_s(st + r * ROWP + seg * 8), sp, ok ? 16 : 0);
    }
    {
        int r = tid >> 2, seg = tid & 3;
        int g = col0 + r;
        int ok = (g < N);
        const __half* sp = Bh + (size_t)(ok ? g : 0) * K + k0 + seg * 8;
        CP16(cvta_s(st + BUFA + r * ROWP + seg * 8), sp, ok ? 16 : 0);
    }
}

// wide: B is 128 rows
__device__ __forceinline__ void load_stage_w(__half* sm, int s,
    hp Ah, int M, hp Bh, int N, int K, int row0, int col0, int k0)
{
    __half* st = sm + s * STGW;
    const int tid = threadIdx.x;
    #pragma unroll
    for (int t = 0; t < 2; t++) {
        int slot = tid + t * 256;
        int r = slot >> 2, seg = slot & 3;
        int g = row0 + r;
        int ok = (g < M);
        const __half* sp = Ah + (size_t)(ok ? g : 0) * K + k0 + seg * 8;
        CP16(cvta_s(st + r * ROWP + seg * 8), sp, ok ? 16 : 0);
    }
    #pragma unroll
    for (int t = 0; t < 2; t++) {
        int slot = tid + t * 256;
        int r = slot >> 2, seg = slot & 3;
        int g = col0 + r;
        int ok = (g < N);
        const __half* sp = Bh + (size_t)(ok ? g : 0) * K + k0 + seg * 8;
        CP16(cvta_s(st + BUFA + r * ROWP + seg * 8), sp, ok ? 16 : 0);
    }
}

// ---------------- BK=32 compute chunks ---------------------------------------
__device__ __forceinline__ void mma_chunk(const __half* st, int wm, int wn,
                                          int row_off, int col_off,
                                          float acc[2][4][4])
{
    #pragma unroll
    for (int kb = 0; kb < BK; kb += 16) {
        uint32_t a[2][4];
        #pragma unroll
        for (int i = 0; i < 2; i++) {
            int off = (wm * 32 + i * 16 + row_off) * ROWP + kb + col_off;
            LDSM4(a[i], cvta_s(st + off));
        }
        uint32_t b4[2][4];
        #pragma unroll
        for (int g = 0; g < 2; g++) {
            int off = (wn * 32 + g * 16 + row_off) * ROWP + kb + col_off;
            LDSM4(b4[g], cvta_s(st + BUFA + off));
        }
        #pragma unroll
        for (int g = 0; g < 2; g++) {
            MMA_F16(acc[0][g*2],   a[0], b4[g][0], b4[g][2]);
            MMA_F16(acc[1][g*2],   a[1], b4[g][0], b4[g][2]);
            MMA_F16(acc[0][g*2+1], a[0], b4[g][1], b4[g][3]);
            MMA_F16(acc[1][g*2+1], a[1], b4[g][1], b4[g][3]);
        }
    }
}

// wide: warp tile 32x64 (acc[2][8][4])
__device__ __forceinline__ void mma_chunk_w(const __half* st, int wm, int wn,
                                            int row_off, int col_off,
                                            float acc[2][8][4])
{
    #pragma unroll
    for (int kb = 0; kb < BK; kb += 16) {
        uint32_t a[2][4];
        #pragma unroll
        for (int i = 0; i < 2; i++) {
            int off = (wm * 32 + i * 16 + row_off) * ROWP + kb + col_off;
            LDSM4(a[i], cvta_s(st + off));
        }
        uint32_t b4[4][4];
        #pragma unroll
        for (int g = 0; g < 4; g++) {
            int off = (wn * 64 + g * 16 + row_off) * ROWP + kb + col_off;
            LDSM4(b4[g], cvta_s(st + BUFA + off));
        }
        #pragma unroll
        for (int g = 0; g < 4; g++) {
            MMA_F16(acc[0][g*2],   a[0], b4[g][0], b4[g][2]);
            MMA_F16(acc[1][g*2],   a[1], b4[g][0], b4[g][2]);
            MMA_F16(acc[0][g*2+1], a[0], b4[g][1], b4[g][3]);
            MMA_F16(acc[1][g*2+1], a[1], b4[g][1], b4[g][3]);
        }
    }
}

#define FRAG_DECLS                                         \
    const int lane = threadIdx.x & 31;                     \
    const int warp = threadIdx.x >> 5;                     \
    const int wm = warp >> 1, wn = warp & 1;               \
    const int mi = lane >> 3, lr8 = lane & 7;              \
    const int row_off = (mi & 1) * 8 + lr8;                \
    const int col_off = (mi >> 1) * 8;

// ---------------- generic K-streamed mainloop (proj) -------------------------
__device__ __forceinline__ void hmma_main(
    hp Ah, int M, hp Bh, int N,
    int K, int row0, int col0, float acc[2][4][4])
{
    extern __shared__ __half smv[];
    FRAG_DECLS

    const int niter = K >> 5;
    load_stage(smv, 0, Ah, M, Bh, N, K, row0, col0, 0);
    CP_COMMIT();
    if (niter > 1) load_stage(smv, 1, Ah, M, Bh, N, K, row0, col0, 32);
    CP_COMMIT();

    for (int it = 0; it < niter; it++) {
        if (it + 2 < niter) {
            load_stage(smv, (it + 2) % STAGES, Ah, M, Bh, N, K,
                       row0, col0, (it + 2) << 5);
            CP_COMMIT();
            CP_WAIT(2);
        } else if (it + 1 < niter) {
            CP_WAIT(1);
        } else {
            CP_WAIT(0);
        }
        __syncthreads();
        mma_chunk(smv + (it % STAGES) * STG, wm, wn, row_off, col_off, acc);
        __syncthreads();
    }
}

// ---------------- wide K-streamed mainloop (av, out) -------------------------
__device__ __forceinline__ void hmma_wide(
    hp Ah, int M, hp Bh, int N,
    int K, int row0, int col0, float acc[2][8][4])
{
    extern __shared__ __half smv[];
    FRAG_DECLS

    const int niter = K >> 5;
    load_stage_w(smv, 0, Ah, M, Bh, N, K, row0, col0, 0);
    CP_COMMIT();
    if (niter > 1) load_stage_w(smv, 1, Ah, M, Bh, N, K, row0, col0, 32);
    CP_COMMIT();

    for (int it = 0; it < niter; it++) {
        if (it + 2 < niter) {
            load_stage_w(smv, (it + 2) % STAGES, Ah, M, Bh, N, K,
                         row0, col0, (it + 2) << 5);
            CP_COMMIT();
            CP_WAIT(2);
        } else if (it + 1 < niter) {
            CP_WAIT(1);
        } else {
            CP_WAIT(0);
        }
        __syncthreads();
        mma_chunk_w(smv + (it % STAGES) * STGW, wm, wn, row_off, col_off, acc);
        __syncthreads();
    }
}

// ---------------- K=128 full-prefetch mainloop (ac, bd) ----------------------
__device__ __forceinline__ void hmma_k128(
    hp Ah, int M, hp Bh, int N, int row0, int col0, float acc[2][4][4])
{
    extern __shared__ __half smv[];
    FRAG_DECLS

    load_stage(smv, 0, Ah, M, Bh, N, DKK, row0, col0, 0);   CP_COMMIT();
    load_stage(smv, 1, Ah, M, Bh, N, DKK, row0, col0, 32);  CP_COMMIT();
    load_stage(smv, 2, Ah, M, Bh, N, DKK, row0, col0, 64);  CP_COMMIT();
    load_stage(smv, 3, Ah, M, Bh, N, DKK, row0, col0, 96);  CP_COMMIT();

    CP_WAIT(3); __syncthreads();
    mma_chunk(smv + 0 * STG, wm, wn, row_off, col_off, acc);
    CP_WAIT(2); __syncthreads();
    mma_chunk(smv + 1 * STG, wm, wn, row_off, col_off, acc);
    CP_WAIT(1); __syncthreads();
    mma_chunk(smv + 2 * STG, wm, wn, row_off, col_off, acc);
    CP_WAIT(0); __syncthreads();
    mma_chunk(smv + 3 * STG, wm, wn, row_off, col_off, acc);
}

// epilogue coordinate helpers
#define EPI_ROW(i, r)   (wm*32 + (i)*16 + grp + ((r) >> 1)*8)
#define EPI_COL(j, r)   (wn*32 + (j)*8 + qid*2 + ((r) & 1))
#define EPI_COLW(j, r)  (wn*64 + (j)*8 + qid*2 + ((r) & 1))
#define EPI_DECLS                                          \
    const int lane = threadIdx.x & 31;                     \
    const int warp = threadIdx.x >> 5;                     \
    const int grp = lane >> 2, qid = lane & 3;             \
    const int wm = warp >> 1, wn = warp & 1;

// ---------------- splits (fp16 convert only) ---------------------------------
__global__ void k_split_hs(const float* __restrict__ hs)
{
    int i = blockIdx.x * blockDim.x + threadIdx.x;
    if (i < MHS*DD) g_hsh[i] = __float2half_rn(hs[i]);
}

__global__ void k_split_pe(const float* __restrict__ pe)
{
    int i = blockIdx.x * blockDim.x + threadIdx.x;
    if (i < PE_N) g_peh[i] = __float2half_rn(pe[i]);
}

__global__ void k_split_w(const float* __restrict__ Wq,
                          const float* __restrict__ Wk,
                          const float* __restrict__ Wv,
                          const float* __restrict__ Wo,
                          const float* __restrict__ Wp)
{
    int i = blockIdx.x * blockDim.x + threadIdx.x;
    if (i >= 5 * DD * DD) return;
    int w = i >> 20, o = i & (DD*DD - 1);
    const float* src = (w == 0) ? Wq : (w == 1) ? Wk : (w == 2) ? Wv
                     : (w == 3) ? Wo : Wp;
    __half* dst = (w == 0) ? g_Wqh : (w == 1) ? g_Wkh : (w == 2) ? g_Wvh
                : (w == 3) ? g_Woh : g_Wph;
    dst[o] = __float2half_rn(src[o]);
}

// ---------------- Q / K / P / V projections, single launch -------------------
__global__ void __launch_bounds__(256, 3)
k_proj(const float* __restrict__ bu, const float* __restrict__ bv)
{
    const int z = blockIdx.z;                     // 0:Q 1:K 2:P 3:V
    if (z == 2 && blockIdx.y >= 16) return;       // P has 16 row tiles
    hp Ah = (z == 2) ? g_peh : g_hsh;
    const int M = (z == 2) ? PP : MHS;
    hp Wh = (z == 0) ? g_Wqh : (z == 1) ? g_Wkh : (z == 2) ? g_Wph : g_Wvh;
    const int row0 = blockIdx.y * 128, col0 = blockIdx.x * 64;
    float acc[2][4][4] = {};
    hmma_main(Ah, M, Wh, DD, DD, row0, col0, acc);
    EPI_DECLS
    #pragma unroll
    for (int i = 0; i < 2; i++)
        #pragma unroll
        for (int j = 0; j < 4; j++)
            #pragma unroll
            for (int r = 0; r < 4; r++) {
                int m = row0 + EPI_ROW(i, r);
                int n = col0 + EPI_COL(j, r);
                int h = n >> 7, d = n & 127;
                float v = acc[i][j][r];
                if (z == 0) {
                    int b = m >> 10, t = m & 1023;
                    size_t idx = ((size_t)(b*HH + h)*TT + t)*DKK + d;
                    g_quh[idx] = __float2half_rn(v + bu[h*DKK + d]);
                    g_qvh[idx] = __float2half_rn(v + bv[h*DKK + d]);
                } else if (z == 1) {
                    int b = m >> 10, t = m & 1023;
                    size_t idx = ((size_t)(b*HH + h)*TT + t)*DKK + d;
                    g_kh[idx] = __float2half_rn(v);
                } else if (z == 2) {
                    if (m < PP) {
                        size_t idx = ((size_t)h*PP + m)*DKK + d;
                        g_ph[idx] = __float2half_rn(v);
                    }
                } else {
                    int b = m >> 10, t = m & 1023;
                    size_t it = ((size_t)(b*HH + h)*DKK + d)*TT + t;  // (b,h,d,t)
                    g_vTh[it] = __float2half_rn(v);
                }
            }
}

// ---------------- AC: scores = qu @ k^T per (b,h)  (K=128 full-prefetch) -----
__global__ void __launch_bounds__(256, 3) k_ac()
{
    const int bh = blockIdx.z;
    const size_t ob = (size_t)bh * TT * DKK;
    const int row0 = blockIdx.y * 128, col0 = blockIdx.x * 64;
    float acc[2][4][4] = {};
    hmma_k128(g_quh + ob, TT, g_kh + ob, TT, row0, col0, acc);
    EPI_DECLS
    float* C = g_scores + (size_t)bh * TT * TT;
    #pragma unroll
    for (int i = 0; i < 2; i++)
        #pragma unroll
        for (int j = 0; j < 4; j++)
            #pragma unroll
            for (int r = 0; r < 4; r++) {
                int m = row0 + EPI_ROW(i, r);
                int n = col0 + EPI_COL(j, r);
                C[(size_t)m * TT + n] = acc[i][j][r];
            }
}

// ---------------- BD: scores[m, n+m-1023] += qv @ p^T (rel-shift fused) ------
__global__ void __launch_bounds__(256, 3) k_bd()
{
    const int bh = blockIdx.z, h = bh & 7;
    const int my = blockIdx.y;
    int cxmin = 896 - 128 * my;
    cxmin = (cxmin > 0) ? (cxmin >> 6) : 0;
    const int cx = blockIdx.x + cxmin;
    const int row0 = my * 128, col0 = cx * 64;
    const size_t oa = (size_t)bh * TT * DKK;
    const size_t op = (size_t)h * PP * DKK;
    float acc[2][4][4] = {};
    hmma_k128(g_qvh + oa, TT, g_ph + op, PP, row0, col0, acc);
    EPI_DECLS
    float* C = g_scores + (size_t)bh * TT * TT;
    #pragma unroll
    for (int i = 0; i < 2; i++)
        #pragma unroll
        for (int j = 0; j < 4; j++)
            #pragma unroll
            for (int r = 0; r < 4; r++) {
                int m = row0 + EPI_ROW(i, r);
                int n = col0 + EPI_COL(j, r);
                if (n < PP) {
                    int k = n + m - 1023;
                    if ((unsigned)k < (unsigned)TT)
                        C[(size_t)m * TT + k] += acc[i][j][r];
                }
            }
}

// ---------------- softmax: warp-per-row, shuffle-only reductions -------------
__global__ void k_softmax()
{
    const int row  = blockIdx.x * 8 + (threadIdx.x >> 5);
    const int lane = threadIdx.x & 31;
    const size_t rowoff = (size_t)row * TT;
    const float4* r4 = reinterpret_cast<const float4*>(g_scores + rowoff);
    const float s = 0.08838834764831845f;        // 1/sqrt(128)

    float4 v[8];
    float m = -1e30f;
    #pragma unroll
    for (int i = 0; i < 8; i++) {
        v[i] = r4[i * 32 + lane];
        v[i].x *= s; v[i].y *= s; v[i].z *= s; v[i].w *= s;
        m = fmaxf(m, fmaxf(fmaxf(v[i].x, v[i].y), fmaxf(v[i].z, v[i].w)));
    }
    #pragma unroll
    for (int o = 16; o > 0; o >>= 1) m = fmaxf(m, __shfl_xor_sync(~0u, m, o));

    float sum = 0.f;
    #pragma unroll
    for (int i = 0; i < 8; i++) {
        v[i].x = __expf(v[i].x - m); v[i].y = __expf(v[i].y - m);
        v[i].z = __expf(v[i].z - m); v[i].w = __expf(v[i].w - m);
        sum += (v[i].x + v[i].y) + (v[i].z + v[i].w);
    }
    #pragma unroll
    for (int o = 16; o > 0; o >>= 1) sum += __shfl_xor_sync(~0u, sum, o);

    float inv = __frcp_rn(sum);
    uint2* dst = reinterpret_cast<uint2*>(g_ath + rowoff);
    #pragma unroll
    for (int i = 0; i < 8; i++) {
        __half2 p01 = __floats2half2_rn(v[i].x * inv, v[i].y * inv);
        __half2 p23 = __floats2half2_rn(v[i].z * inv, v[i].w * inv);
        uint2 pk;
        pk.x = *reinterpret_cast<uint32_t*>(&p01);
        pk.y = *reinterpret_cast<uint32_t*>(&p23);
        dst[i * 32 + lane] = pk;
    }
}

// ---------------- AV: o = attn @ v per (b,h)  (wide: full d in one tile) -----
__global__ void __launch_bounds__(256, 2) k_av()
{
    const int bh = blockIdx.y, b = bh >> 3, h = bh & 7;
    const size_t oa = (size_t)bh * TT * TT;
    const size_t ov = (size_t)bh * DKK * TT;
    const int row0 = blockIdx.x * 128;
    float acc[2][8][4] = {};
    hmma_wide(g_ath + oa, TT, g_vTh + ov, DKK, TT, row0, 0, acc);
    EPI_DECLS
    #pragma unroll
    for (int i = 0; i < 2; i++)
        #pragma unroll
        for (int j = 0; j < 8; j++)
            #pragma unroll
            for (int r = 0; r < 4; r++) {
                int m = row0 + EPI_ROW(i, r);
                int n = EPI_COLW(j, r);             // head-dim 0..127
                size_t idx = ((size_t)(b*TT + m)*HH + h)*DKK + n; // (b,t,h,d)
                g_oh[idx] = __float2half_rn(acc[i][j][r]);
            }
}

// ---------------- output projection (wide 128x128 tiles) ---------------------
__global__ void __launch_bounds__(256, 2) k_out(float* __restrict__ out)
{
    const int row0 = blockIdx.y * 128, col0 = blockIdx.x * 128;
    float acc[2][8][4] = {};
    hmma_wide(g_oh, MHS, g_Woh, DD, DD, row0, col0, acc);
    EPI_DECLS
    #pragma unroll
    for (int i = 0; i < 2; i++)
        #pragma unroll
        for (int j = 0; j < 8; j++)
            #pragma unroll
            for (int r = 0; r < 4; r++) {
                int m = row0 + EPI_ROW(i, r);
                int n = col0 + EPI_COLW(j, r);
                out[(size_t)m * DD + n] = acc[i][j][r];
            }
}

// ---------------- launch ----------------------------------------------------
extern "C" void kernel_launch(void* const* d_in, const int* in_sizes, int n_in,
                              void* d_out, int out_size)
{
    const float* hs = (const float*)d_in[0];
    const float* pe = (const float*)d_in[1];
    const float* Wq = (const float*)d_in[2];
    const float* Wk = (const float*)d_in[3];
    const float* Wv = (const float*)d_in[4];
    const float* Wo = (const float*)d_in[5];
    const float* Wp = (const float*)d_in[6];
    const float* bu = (const float*)d_in[7];
    const float* bv = (const float*)d_in[8];
    float* out = (float*)d_out;

    static int attr_done = 0;
    if (!attr_done) {
        cudaFuncSetAttribute(k_proj, cudaFuncAttributeMaxDynamicSharedMemorySize, DYN);
        cudaFuncSetAttribute(k_ac,   cudaFuncAttributeMaxDynamicSharedMemorySize, DYN4);
        cudaFuncSetAttribute(k_bd,   cudaFuncAttributeMaxDynamicSharedMemorySize, DYN4);
        cudaFuncSetAttribute(k_av,   cudaFuncAttributeMaxDynamicSharedMemorySize, DYNW);
        cudaFuncSetAttribute(k_out,  cudaFuncAttributeMaxDynamicSharedMemorySize, DYNW);
        attr_done = 1;
    }

    // launch order keeps k_bd at position 6 so ncu (-s 5 -c 1) profiles it
    k_split_hs<<<(MHS*DD + 255)/256, 256>>>(hs);
    k_split_pe<<<(PE_N + 255)/256, 256>>>(pe);
    k_split_w <<<(5*DD*DD + 255)/256, 256>>>(Wq, Wk, Wv, Wo, Wp);

    k_proj<<<dim3(16, 32, 4), 256, DYN>>>(bu, bv);
    k_ac <<<dim3(16, 8, BATCH*HH), 256, DYN4>>>();
    k_bd <<<dim3(18, 8, BATCH*HH), 256, DYN4>>>();
    k_softmax<<<BATCH*HH*TT/8, 256>>>();
    k_av <<<dim3(8, BATCH*HH), 256, DYNW>>>();
    k_out<<<dim3(8, 32), 256, DYNW>>>(out);
}